// round 6
// baseline (speedup 1.0000x reference)
#include <cuda_runtime.h>
#include <cuda_bf16.h>

#define NLEV  256
#define NBINS 4096
#define VPT   2     // float4 per stream per thread => 8 elements/thread
#define FBIG  3.402823466e38f

// Exact reference symbol for scalar x over shared codebook su[256].
__device__ __forceinline__ int sym_exact(const float* su, float x)
{
    int q = 0;                                  // count(u < x), branchless
    #pragma unroll
    for (int s = 128; s >= 1; s >>= 1) {
        if (su[q + s - 1] < x) q += s;
    }
    int c = q < 1 ? 1 : (q > NLEV - 1 ? NLEV - 1 : q);
    float l = su[c - 1], r = su[c];
    return (fabsf(x - l) <= fabsf(x - r)) ? c - 1 : c;
}

__global__ void __launch_bounds__(256, 5)
agc_quant_kernel(const float4* __restrict__ in4,
                 const float4* __restrict__ mn4,
                 const float*  __restrict__ uvals,
                 float* __restrict__ out_dq,
                 float* __restrict__ out_sym,
                 int n4, int n)
{
    __shared__ float  su[NLEV];                 // 1 KB scalar codebook
    __shared__ float2 lutv[NBINS];              // 32 KB: {value, symbol} or sentinel
    __shared__ short  bsym[NBINS + 2];          // 8 KB setup scratch

    const int tid  = threadIdx.x;
    const int bdim = blockDim.x;

    if (tid < NLEV) su[tid] = uvals[tid];
    __syncthreads();

    const float lo    = su[0];
    const float hi    = su[NLEV - 1];
    const float w     = (hi - lo) * (1.0f / NBINS);
    const float inv_w = (float)NBINS / (hi - lo);

    // ---- Setup: boundary symbols at guard-shifted sample points ----
    // t_j = start_j - w/16  (monotone symbol(): bin pure iff sym const on
    // [t_b, t_{b+2}] which strictly contains the bin + fp-slop margin).
    for (int j = tid; j < NBINS + 2; j += bdim) {
        float xq;
        if (j == 0)               xq = -FBIG;
        else if (j == NBINS + 1)  xq =  FBIG;
        else                      xq = fmaf((float)j - 0.0625f, w, lo);
        bsym[j] = (short)sym_exact(su, xq);
    }
    __syncthreads();

    for (int b = tid; b < NBINS; b += bdim) {
        int s0 = bsym[b];
        int s1 = bsym[b + 2];
        float2 rec;
        if (s0 == s1) rec = make_float2(su[s0], (float)s0);     // pure bin
        else          rec = make_float2(0.0f, -(float)(s0 + 1)); // sentinel+seed
        lutv[b] = rec;
    }
    __syncthreads();

    const int tile  = bdim * VPT;
    const int gstep = gridDim.x * tile;

    for (int base = blockIdx.x * tile + tid; base < n4; base += gstep) {

        if (base + (VPT - 1) * bdim < n4) {
            float4 x[VPT], mm[VPT];
            #pragma unroll
            for (int j = 0; j < VPT; j++) x[j]  = __ldcs(&in4[base + j * bdim]);
            #pragma unroll
            for (int j = 0; j < VPT; j++) mm[j] = __ldcs(&mn4[base + j * bdim]);

            float v[4 * VPT];
            #pragma unroll
            for (int j = 0; j < VPT; j++) {
                v[4*j+0] = x[j].x - mm[j].x;
                v[4*j+1] = x[j].y - mm[j].y;
                v[4*j+2] = x[j].z - mm[j].z;
                v[4*j+3] = x[j].w - mm[j].w;
            }

            float dq[4 * VPT], sy[4 * VPT];

            // Fast path: one LDS.64 per element.
            #pragma unroll
            for (int e = 0; e < 4 * VPT; e++) {
                int bb = (int)((v[e] - lo) * inv_w);
                bb = bb < 0 ? 0 : (bb > NBINS - 1 ? NBINS - 1 : bb);
                float2 r = lutv[bb];
                dq[e] = r.x;
                sy[e] = r.y;
            }
            // Rare resolve (~12% of lanes): seeded scan + exact tie-break.
            #pragma unroll
            for (int e = 0; e < 4 * VPT; e++) {
                if (sy[e] < 0.0f) {
                    int q = (int)(-sy[e]) - 1;
                    while (q < NLEV && su[q] < v[e]) ++q;
                    int c = q < 1 ? 1 : (q > NLEV - 1 ? NLEV - 1 : q);
                    float l = su[c - 1], r = su[c];
                    bool tl = fabsf(v[e] - l) <= fabsf(v[e] - r);
                    sy[e] = (float)(tl ? c - 1 : c);
                    dq[e] = tl ? l : r;
                }
            }

            #pragma unroll
            for (int j = 0; j < VPT; j++) {
                __stcs(&reinterpret_cast<float4*>(out_dq)[base + j * bdim],
                       make_float4(dq[4*j+0] + mm[j].x, dq[4*j+1] + mm[j].y,
                                   dq[4*j+2] + mm[j].z, dq[4*j+3] + mm[j].w));
                __stcs(&reinterpret_cast<float4*>(out_sym)[base + j * bdim],
                       make_float4(sy[4*j+0], sy[4*j+1], sy[4*j+2], sy[4*j+3]));
            }
        } else {
            // guarded path: exact per element
            #pragma unroll
            for (int j = 0; j < VPT; j++) {
                int i = base + j * bdim;
                if (i >= n4) break;
                float4 x = in4[i];
                float4 m = mn4[i];
                float vv[4] = { x.x - m.x, x.y - m.y, x.z - m.z, x.w - m.w };
                float dq[4], sy[4];
                #pragma unroll
                for (int k = 0; k < 4; k++) {
                    int s = sym_exact(su, vv[k]);
                    sy[k] = (float)s;
                    dq[k] = su[s];
                }
                reinterpret_cast<float4*>(out_dq)[i] =
                    make_float4(dq[0] + m.x, dq[1] + m.y, dq[2] + m.z, dq[3] + m.w);
                reinterpret_cast<float4*>(out_sym)[i] =
                    make_float4(sy[0], sy[1], sy[2], sy[3]);
            }
        }
    }

    // Scalar float tail (n % 4 != 0) — block 0 only.
    if (blockIdx.x == 0) {
        const float* in1 = reinterpret_cast<const float*>(in4);
        const float* mn1 = reinterpret_cast<const float*>(mn4);
        for (int i = n4 * 4 + tid; i < n; i += bdim) {
            float vv = in1[i] - mn1[i];
            int s = sym_exact(su, vv);
            out_sym[i] = (float)s;
            out_dq[i]  = su[s] + mn1[i];
        }
    }
}

extern "C" void kernel_launch(void* const* d_in, const int* in_sizes, int n_in,
                              void* d_out, int out_size)
{
    const float* inputs = (const float*)d_in[0];
    const float* means  = (const float*)d_in[1];
    const float* uvals  = (const float*)d_in[2];
    float* out = (float*)d_out;

    const int n  = out_size / 2;
    const int n4 = n / 4;

    float* out_dq  = out;
    float* out_sym = out + n;

    const int threads = 256;
    int blocks = 740;                        // 5 CTAs/SM on 148 SMs, grid-stride
    int maxb = (n4 + threads * VPT - 1) / (threads * VPT);
    if (blocks > maxb && maxb > 0) blocks = maxb;
    if (blocks < 1) blocks = 1;

    agc_quant_kernel<<<blocks, threads>>>(
        (const float4*)inputs, (const float4*)means, uvals,
        out_dq, out_sym, n4, n);
}

// round 7
// speedup vs baseline: 1.0907x; 1.0907x over previous
#include <cuda_runtime.h>
#include <cuda_bf16.h>

#define NLEV  256
#define NBINS 4096
#define BPT   (NBINS / 256)
#define VPT   2     // float4 per stream per thread => 8 elements/thread
#define FBIG  3.402823466e38f

// Monotone order-preserving float<->uint key (total order on finite floats).
__device__ __forceinline__ unsigned okey(float f) {
    unsigned u = __float_as_uint(f);
    return (u & 0x80000000u) ? ~u : (u | 0x80000000u);
}
__device__ __forceinline__ float oinv(unsigned k) {
    return __uint_as_float((k & 0x80000000u) ? (k ^ 0x80000000u) : ~k);
}

__global__ void __launch_bounds__(256, 5)
agc_quant_kernel(const float4* __restrict__ in4,
                 const float4* __restrict__ mn4,
                 const float*  __restrict__ uvals,
                 float* __restrict__ out_dq,
                 float* __restrict__ out_sym,
                 int n4, int n)
{
    __shared__ float Ts[NLEV];        // scalar thresholds, Ts[255] = +FBIG pad
    __shared__ float su[NLEV];        // codebook (dequant values)
    __shared__ float Tr[NLEV * 32];   // 32 KB replicated thresholds: Tr[j*32+lane]
    __shared__ short slut[NBINS];     // 8 KB conservative count seeds

    const int tid  = threadIdx.x;
    const int lane = tid & 31;
    const int bdim = blockDim.x;

    if (tid < NLEV) su[tid] = uvals[tid];
    __syncthreads();

    // ---- Exact decision thresholds: T[i-1] = largest float v for which the
    // reference tie-break (fabsf(v-u[i-1]) <= fabsf(v-u[i])) picks symbol i-1.
    // Predicate is monotone in v -> exact via binary search on ordered keys.
    if (tid >= 1 && tid < NLEV) {
        float l = su[tid - 1], r = su[tid];
        unsigned klo = okey(l);   // P(l) = true  (0 <= r-l)
        unsigned khi = okey(r);   // P(r) = false (r-l <= 0 fails, values distinct)
        while (khi - klo > 1u) {
            unsigned km = klo + ((khi - klo) >> 1);
            float vm = oinv(km);
            if (fabsf(vm - l) <= fabsf(vm - r)) klo = km; else khi = km;
        }
        Ts[tid - 1] = oinv(klo);
    }
    if (tid == 0) Ts[NLEV - 1] = FBIG;
    __syncthreads();

    // Replicated threshold table (conflict-free accesses later).
    for (int i = tid; i < NLEV * 32; i += bdim)
        Tr[i] = Ts[i >> 5];
    __syncthreads();

    const float lo    = su[0];
    const float hi    = su[NLEV - 1];
    const float w     = (hi - lo) * (1.0f / NBINS);
    const float inv_w = (float)NBINS / (hi - lo);
    const float c0    = -lo * inv_w;              // bin = trunc(fma(v, inv_w, c0))

    // ---- Seed LUT: slut[b] = count(T < fmaf(b-1, w, lo)); one-bin guard makes
    // it a provable lower bound of count(T < v) for any v that maps to bin b.
    {
        const int b0 = tid * BPT;
        float x0 = fmaf((float)(b0 - 1), w, lo);
        int q = 0;                                 // branchless count over padded 256
        #pragma unroll
        for (int s = 128; s >= 1; s >>= 1)
            if (Tr[((q + s - 1) << 5) + lane] < x0) q += s;
        #pragma unroll
        for (int j = 0; j < BPT; j++) {
            int b = b0 + j;
            float xb = fmaf((float)(b - 1), w, lo);
            while (q < NLEV - 1 && Tr[(q << 5) + lane] < xb) ++q;
            slut[b] = (short)q;
        }
    }
    __syncthreads();

    const int tile  = bdim * VPT;
    const int gstep = gridDim.x * tile;

    for (int base = blockIdx.x * tile + tid; base < n4; base += gstep) {

        if (base + (VPT - 1) * bdim < n4) {
            float4 x[VPT], mm[VPT];
            #pragma unroll
            for (int j = 0; j < VPT; j++) x[j]  = __ldcs(&in4[base + j * bdim]);
            #pragma unroll
            for (int j = 0; j < VPT; j++) mm[j] = __ldcs(&mn4[base + j * bdim]);

            float v[4 * VPT];
            #pragma unroll
            for (int j = 0; j < VPT; j++) {
                v[4*j+0] = x[j].x - mm[j].x;
                v[4*j+1] = x[j].y - mm[j].y;
                v[4*j+2] = x[j].z - mm[j].z;
                v[4*j+3] = x[j].w - mm[j].w;
            }

            int q[4 * VPT];
            #pragma unroll
            for (int e = 0; e < 4 * VPT; e++) {
                int b = (int)fmaf(v[e], inv_w, c0);
                b = b < 0 ? 0 : (b > NBINS - 1 ? NBINS - 1 : b);
                q[e] = slut[b];                    // conservative seed
            }
            #pragma unroll
            for (int e = 0; e < 4 * VPT; e++) {
                int p = q[e];                      // exact count(T < v): ~1.1 checks
                while (p < NLEV - 1 && Tr[(p << 5) + lane] < v[e]) ++p;
                q[e] = p;
            }

            float dq[4 * VPT], sy[4 * VPT];
            #pragma unroll
            for (int e = 0; e < 4 * VPT; e++) {
                sy[e] = (float)q[e];
                dq[e] = su[q[e]];                  // small-table LDS (~3 phases)
            }
            #pragma unroll
            for (int j = 0; j < VPT; j++) {
                __stcs(&reinterpret_cast<float4*>(out_dq)[base + j * bdim],
                       make_float4(dq[4*j+0] + mm[j].x, dq[4*j+1] + mm[j].y,
                                   dq[4*j+2] + mm[j].z, dq[4*j+3] + mm[j].w));
                __stcs(&reinterpret_cast<float4*>(out_sym)[base + j * bdim],
                       make_float4(sy[4*j+0], sy[4*j+1], sy[4*j+2], sy[4*j+3]));
            }
        } else {
            // guarded path: full branchless search (exact, rare)
            #pragma unroll
            for (int j = 0; j < VPT; j++) {
                int i = base + j * bdim;
                if (i >= n4) break;
                float4 x = in4[i];
                float4 m = mn4[i];
                float vv[4] = { x.x - m.x, x.y - m.y, x.z - m.z, x.w - m.w };
                float dq[4], sy[4];
                #pragma unroll
                for (int k = 0; k < 4; k++) {
                    int p = 0;
                    #pragma unroll
                    for (int s = 128; s >= 1; s >>= 1)
                        if (Tr[((p + s - 1) << 5) + lane] < vv[k]) p += s;
                    sy[k] = (float)p;
                    dq[k] = su[p];
                }
                reinterpret_cast<float4*>(out_dq)[i] =
                    make_float4(dq[0] + m.x, dq[1] + m.y, dq[2] + m.z, dq[3] + m.w);
                reinterpret_cast<float4*>(out_sym)[i] =
                    make_float4(sy[0], sy[1], sy[2], sy[3]);
            }
        }
    }

    // Scalar float tail (n % 4 != 0) — block 0 only.
    if (blockIdx.x == 0) {
        const float* in1 = reinterpret_cast<const float*>(in4);
        const float* mn1 = reinterpret_cast<const float*>(mn4);
        for (int i = n4 * 4 + tid; i < n; i += bdim) {
            float vv = in1[i] - mn1[i];
            int p = 0;
            #pragma unroll
            for (int s = 128; s >= 1; s >>= 1)
                if (Tr[((p + s - 1) << 5) + lane] < vv) p += s;
            out_sym[i] = (float)p;
            out_dq[i]  = su[p] + mn1[i];
        }
    }
}

extern "C" void kernel_launch(void* const* d_in, const int* in_sizes, int n_in,
                              void* d_out, int out_size)
{
    const float* inputs = (const float*)d_in[0];
    const float* means  = (const float*)d_in[1];
    const float* uvals  = (const float*)d_in[2];
    float* out = (float*)d_out;

    const int n  = out_size / 2;
    const int n4 = n / 4;

    float* out_dq  = out;
    float* out_sym = out + n;

    const int threads = 256;
    int blocks = 740;                        // 5 CTAs/SM on 148 SMs, grid-stride
    int maxb = (n4 + threads * VPT - 1) / (threads * VPT);
    if (blocks > maxb && maxb > 0) blocks = maxb;
    if (blocks < 1) blocks = 1;

    agc_quant_kernel<<<blocks, threads>>>(
        (const float4*)inputs, (const float4*)means, uvals,
        out_dq, out_sym, n4, n);
}